// round 14
// baseline (speedup 1.0000x reference)
#include <cuda_runtime.h>

// LocalCosineSimilarity — 4-cols-per-lane streaming box filter (v4).
// Lane owns 4 consecutive columns: float4 LDG (4x MLP), horizontal 11-tap via
// warp prefix scan + local prefixes, float4 smem ring for vertical window,
// float4 STG. One warp per CTA, fully warp-autonomous.

#define IMG_W  1024
#define IMG_H  1024
#define KW     11
#define HALO   5
#define OLANES 28                 // lanes producing output (4 cols each)
#define WC     (OLANES * 4)       // 112 output cols per CTA
#define CH     64                 // output rows per CTA
#define NR     (CH + 2 * HALO)    // 74 input rows streamed
#define NSTRIP 10                 // ceil(1024/112), last strip clamped (overlap ok)
#define FULLM  0xffffffffu

__global__ void __launch_bounds__(32)
lcs_v4_kernel(const float* __restrict__ xg, const float* __restrict__ yg,
              float* __restrict__ outg)
{
    __shared__ float4 ring[KW][3][OLANES];   // 14.8 KB; lane-private columns

    const int lane     = threadIdx.x;
    const int out_base = min((int)blockIdx.x * WC, IMG_W - WC);  // clamp last strip
    const int gy0      = blockIdx.y * CH;
    const int b        = blockIdx.z;

    const size_t HW = (size_t)IMG_W * IMG_H;
    const float* xb = xg + (size_t)b * 3 * HW;
    const float* yb = yg + (size_t)b * 3 * HW;
    float* outb = outg + (size_t)b * HW;

    // lane's 4 loaded cols: [c0, c0+3]; covers cols out_base-8 .. out_base+119.
    // Window for output m needs loaded idx m+3..m+13 (offset 8-5=3).
    const int  c0     = out_base - 8 + 4 * lane;
    const bool colv   = (c0 >= 0) && (c0 + 3 < IMG_W);   // all-or-nothing (4 | 1024)
    const bool active = lane < OLANES;

    {   // zero the ring
        const float4 z = make_float4(0.f, 0.f, 0.f, 0.f);
        float4* rp = &ring[0][0][0];
        for (int i = lane; i < KW * 3 * OLANES; i += 32) rp[i] = z;
    }
    __syncwarp();

    // channel-reduced products for 4 pixels of one input row
    auto loadrow = [&](int r, float4& pxx, float4& pyy, float4& pxy) {
        pxx = pyy = pxy = make_float4(0.f, 0.f, 0.f, 0.f);
        const int gy = gy0 - HALO + r;
        if (r < NR && (unsigned)gy < (unsigned)IMG_H && colv) {
            const size_t o = (size_t)gy * IMG_W + c0;
            #pragma unroll
            for (int ch = 0; ch < 3; ++ch) {
                const float4 xv = *reinterpret_cast<const float4*>(xb + (size_t)ch * HW + o);
                const float4 yv = *reinterpret_cast<const float4*>(yb + (size_t)ch * HW + o);
                pxx.x = fmaf(xv.x, xv.x, pxx.x); pxx.y = fmaf(xv.y, xv.y, pxx.y);
                pxx.z = fmaf(xv.z, xv.z, pxx.z); pxx.w = fmaf(xv.w, xv.w, pxx.w);
                pyy.x = fmaf(yv.x, yv.x, pyy.x); pyy.y = fmaf(yv.y, yv.y, pyy.y);
                pyy.z = fmaf(yv.z, yv.z, pyy.z); pyy.w = fmaf(yv.w, yv.w, pyy.w);
                pxy.x = fmaf(xv.x, yv.x, pxy.x); pxy.y = fmaf(xv.y, yv.y, pxy.y);
                pxy.z = fmaf(xv.z, yv.z, pxy.z); pxy.w = fmaf(xv.w, yv.w, pxy.w);
            }
        }
    };

    // Horizontal 11-tap for lane's 4 outputs.
    // P[q] = exclusive prefix of loaded row. H[m] = P[m+14] - P[m+3], m = 4*lane+j.
    // S[a] = exclusive lane-sum scan; note S[l+1] = Sin[l] (inclusive scan, local).
    auto hwin = [&](const float4 v, float4& H) {
        const float lp2 = v.x + v.y;
        const float lp3 = lp2 + v.z;
        float Sin = lp3 + v.w;                 // lane sum -> inclusive scan
        #pragma unroll
        for (int o = 1; o < 32; o <<= 1) {
            const float t = __shfl_up_sync(FULLM, Sin, o);
            if (lane >= o) Sin += t;
        }
        const float S3   = __shfl_down_sync(FULLM, Sin, 2);   // S[l+3]
        const float S4   = __shfl_down_sync(FULLM, Sin, 3);   // S[l+4]
        const float l1_1 = __shfl_down_sync(FULLM, v.x, 1);   // lp1[l+1]
        const float l2_1 = __shfl_down_sync(FULLM, lp2, 1);   // lp2[l+1]
        const float l2_3 = __shfl_down_sync(FULLM, lp2, 3);   // lp2[l+3]
        const float l3_3 = __shfl_down_sync(FULLM, lp3, 3);   // lp3[l+3]
        const float l1_4 = __shfl_down_sync(FULLM, v.x, 4);   // lp1[l+4]
        H.x = (S3 + l2_3) - (Sin - v.w);       // P[4l+14] - P[4l+3]
        H.y = (S3 + l3_3) -  Sin;              // P[4l+15] - P[4l+4]
        H.z =  S4         - (Sin + l1_1);      // P[4l+16] - P[4l+5]
        H.w = (S4 + l1_4) - (Sin + l2_1);      // P[4l+17] - P[4l+6]
    };

    float4 nxx, nyy, nxy;
    loadrow(0, nxx, nyy, nxy);

    float4 axx = make_float4(0.f, 0.f, 0.f, 0.f);
    float4 ayy = axx, axy = axx;
    int slot = 0;

    #pragma unroll 1
    for (int r = 0; r < NR; ++r) {
        const float4 cxx = nxx, cyy = nyy, cxy = nxy;
        loadrow(r + 1, nxx, nyy, nxy);         // in flight during shuffle trees

        float4 Hxx, Hyy, Hxy;
        hwin(cxx, Hxx);
        hwin(cyy, Hyy);
        hwin(cxy, Hxy);

        if (active) {
            float4 o0 = ring[slot][0][lane];
            axx.x += Hxx.x - o0.x; axx.y += Hxx.y - o0.y;
            axx.z += Hxx.z - o0.z; axx.w += Hxx.w - o0.w;
            ring[slot][0][lane] = Hxx;

            float4 o1 = ring[slot][1][lane];
            ayy.x += Hyy.x - o1.x; ayy.y += Hyy.y - o1.y;
            ayy.z += Hyy.z - o1.z; ayy.w += Hyy.w - o1.w;
            ring[slot][1][lane] = Hyy;

            float4 o2 = ring[slot][2][lane];
            axy.x += Hxy.x - o2.x; axy.y += Hxy.y - o2.y;
            axy.z += Hxy.z - o2.z; axy.w += Hxy.w - o2.w;
            ring[slot][2][lane] = Hxy;

            if (r >= 2 * HALO) {
                const int ro = gy0 + r - 2 * HALO;
                float4 o4;
                o4.x = axy.x / (sqrtf(axx.x) * sqrtf(ayy.x) + 1e-6f);
                o4.y = axy.y / (sqrtf(axx.y) * sqrtf(ayy.y) + 1e-6f);
                o4.z = axy.z / (sqrtf(axx.z) * sqrtf(ayy.z) + 1e-6f);
                o4.w = axy.w / (sqrtf(axx.w) * sqrtf(ayy.w) + 1e-6f);
                *reinterpret_cast<float4*>(outb + (size_t)ro * IMG_W + out_base + 4 * lane) = o4;
            }
        }
        if (++slot == KW) slot = 0;
    }
}

extern "C" void kernel_launch(void* const* d_in, const int* in_sizes, int n_in,
                              void* d_out, int out_size)
{
    const float* x = (const float*)d_in[0];
    const float* y = (const float*)d_in[1];
    float* out = (float*)d_out;

    dim3 grid(NSTRIP,            // 10 column strips (last clamped/overlapping)
              IMG_H / CH,        // 16
              8);                // batch -> 1280 CTAs
    lcs_v4_kernel<<<grid, 32>>>(x, y, out);
}